// round 9
// baseline (speedup 1.0000x reference)
#include <cuda_runtime.h>
#include <cuda_fp16.h>
#include <cstdint>

constexpr int NA = 1024, NB = 1024, DD = 512, KK = 256;

// Device scratch: only F split + stage-1 outputs (X is converted in-kernel)
__device__ __half g_Fh[KK * DD];
__device__ __half g_Fl[KK * DD];
__device__ __half g_Ph[NA * KK];
__device__ __half g_Mb[NB * KK];

// ---------------------------------------------------------------------------
// PTX helpers
// ---------------------------------------------------------------------------
__device__ __forceinline__ uint32_t smem_u32(const void* p) {
    uint32_t r;
    asm("{ .reg .u64 t; cvta.to.shared.u64 t, %1; cvt.u32.u64 %0, t; }" : "=r"(r) : "l"(p));
    return r;
}
__device__ __forceinline__ void cp16(uint32_t dst, const void* src) {
    asm volatile("cp.async.cg.shared.global [%0], [%1], 16;" :: "r"(dst), "l"(src) : "memory");
}
__device__ __forceinline__ void cp_commit() { asm volatile("cp.async.commit_group;" ::: "memory"); }
__device__ __forceinline__ void cp_wait1()  { asm volatile("cp.async.wait_group 1;" ::: "memory"); }
__device__ __forceinline__ void cp_wait0()  { asm volatile("cp.async.wait_group 0;" ::: "memory"); }

__device__ __forceinline__ void ldm_x4(uint32_t* r, uint32_t addr) {
    asm volatile("ldmatrix.sync.aligned.m8n8.x4.shared.b16 {%0,%1,%2,%3}, [%4];"
                 : "=r"(r[0]), "=r"(r[1]), "=r"(r[2]), "=r"(r[3]) : "r"(addr));
}
__device__ __forceinline__ void mma_f16(float* d, const uint32_t* a, const uint32_t* b) {
    asm volatile(
        "mma.sync.aligned.m16n8k16.row.col.f32.f16.f16.f32 "
        "{%0,%1,%2,%3}, {%4,%5,%6,%7}, {%8,%9}, {%0,%1,%2,%3};"
        : "+f"(d[0]), "+f"(d[1]), "+f"(d[2]), "+f"(d[3])
        : "r"(a[0]), "r"(a[1]), "r"(a[2]), "r"(a[3]), "r"(b[0]), "r"(b[1]));
}

// fp16 tile geometry (F arrays, stage-2 arrays)
constexpr uint32_t TSTR = 144;
constexpr uint32_t ARR  = 64 * TSTR;   // 9216

__device__ __forceinline__ uint32_t a_addr(uint32_t base, int row0, int lane, int koff) {
    return base + (uint32_t)(row0 + (lane & 15)) * TSTR + (uint32_t)koff + ((lane >> 4) << 4);
}
__device__ __forceinline__ uint32_t b_addr(uint32_t base, int row0, int lane, int koff) {
    return base + (uint32_t)(row0 + (lane & 7) + ((lane >> 4) << 3)) * TSTR
                + (uint32_t)koff + (((lane >> 3) & 1) << 4);
}

__device__ __forceinline__ uint32_t hpack2(float2 v) {
    __half2 t = __float22half2_rn(v);
    return *reinterpret_cast<uint32_t*>(&t);
}
__device__ __forceinline__ uint32_t lpack2(float2 v, uint32_t hbits) {
    __half2 h = *reinterpret_cast<__half2*>(&hbits);
    float2 hf = __half22float2(h);
    return hpack2(make_float2(v.x - hf.x, v.y - hf.y));
}

// ---------------------------------------------------------------------------
// Kernel 0: split feats fp32 -> (Fh, Fl). 64 blocks x 256 thr, 8 elem/thread.
// ---------------------------------------------------------------------------
__global__ __launch_bounds__(256) void convertF_kernel(const float* __restrict__ feats)
{
    const int base = (blockIdx.x * 256 + threadIdx.x) * 8;
    const float4 v0 = *reinterpret_cast<const float4*>(feats + base);
    const float4 v1 = *reinterpret_cast<const float4*>(feats + base + 4);
    uint4 h, l;
    h.x = hpack2(make_float2(v0.x, v0.y)); l.x = lpack2(make_float2(v0.x, v0.y), h.x);
    h.y = hpack2(make_float2(v0.z, v0.w)); l.y = lpack2(make_float2(v0.z, v0.w), h.y);
    h.z = hpack2(make_float2(v1.x, v1.y)); l.z = lpack2(make_float2(v1.x, v1.y), h.z);
    h.w = hpack2(make_float2(v1.z, v1.w)); l.w = lpack2(make_float2(v1.z, v1.w), h.w);
    *reinterpret_cast<uint4*>(g_Fh + base) = h;
    *reinterpret_cast<uint4*>(g_Fl + base) = l;
}

// ---------------------------------------------------------------------------
// Stage 1 (X fully fused): C[2048x256] = X · F^T
//   X arrives fp32 via cp.async; A-fragments assembled in-register with
//   on-the-fly fp16 hi (+ lo for b rows). F uses precomputed fp16 + ldmatrix.
//   a rows: Xh·Fh ; b rows: XhFh + XhFl + XlFh
// Tile 64x64, 256 threads (8 warps, warp tile 16x32), k-chunk 64,
// 3 smem buffers, 1 sync/chunk. grid (4, 32).
// ---------------------------------------------------------------------------
constexpr uint32_t XSTR  = 272;              // 64 fp32 = 256B + 16B pad
constexpr uint32_t XARR  = 64 * XSTR;        // 17408
constexpr uint32_t S1_BUF = XARR + 2 * ARR;  // Xf, Fh, Fl = 35840
constexpr int S1_SMEM = 3 * S1_BUF;          // 107520

__global__ __launch_bounds__(256) void stage1_mma(
    const float* __restrict__ a, const float* __restrict__ b)
{
    extern __shared__ char dsm[];
    const uint32_t sb = smem_u32(dsm);

    const int tid = threadIdx.x;
    const int lane = tid & 31;
    const int wid = tid >> 5;
    const int wm = wid & 3;          // 4 warp rows x 16
    const int wn = wid >> 2;         // 2 warp cols x 32

    const int m0 = blockIdx.y * 64;
    const int n0 = blockIdx.x * 64;
    const bool isA = (m0 < NA);

    const float*  pX  = isA ? (a + (size_t)m0 * DD) : (b + (size_t)(m0 - NA) * DD);
    const __half* pFh = g_Fh + (size_t)n0 * DD;
    const __half* pFl = g_Fl + (size_t)n0 * DD;

    auto load_chunk = [&](int ch, uint32_t bufOff) {
        const int d0 = ch * 64;
        // X fp32: 64 rows x 16 slots(16B) = 1024 cp16 -> 4/thread
#pragma unroll
        for (int u = 0; u < 4; u++) {
            const int v = tid + u * 256;
            const int r = v >> 4, s = v & 15;
            cp16(sb + bufOff + (uint32_t)r * XSTR + (uint32_t)(s << 4),
                 pX + (size_t)r * DD + d0 + s * 4);
        }
        // Fh (+Fl if b): 64 rows x 8 slots = 512 cp16 each -> 2/thread each
#pragma unroll
        for (int u = 0; u < 2; u++) {
            const int v = tid + u * 256;
            const int r = v >> 3, s = v & 7;
            const uint32_t sm = sb + bufOff + XARR + (uint32_t)r * TSTR + (uint32_t)(s << 4);
            cp16(sm, pFh + (size_t)r * DD + d0 + s * 8);
            if (!isA) cp16(sm + ARR, pFl + (size_t)r * DD + d0 + s * 8);
        }
        cp_commit();
    };

    constexpr int NCH = DD / 64;   // 8
    load_chunk(0, 0);
    load_chunk(1, S1_BUF);

    float acc[4][4] = {};
    const int g = lane >> 2, t = lane & 3;

    for (int ch = 0; ch < NCH; ch++) {
        if (ch + 1 < NCH) cp_wait1(); else cp_wait0();
        __syncthreads();
        if (ch + 2 < NCH) load_chunk(ch + 2, (uint32_t)((ch + 2) % 3) * S1_BUF);

        const uint32_t bufOff = (uint32_t)(ch % 3) * S1_BUF;
        const char* xb = dsm + bufOff;
        const uint32_t fb = sb + bufOff + XARR;

#pragma unroll
        for (int ks = 0; ks < 4; ks++) {
            const int koff = ks * 32;              // bytes into fp16 row (16 halves)
            // ---- A fragment from fp32 smem: hi (+ lo) ----
            const uint32_t kb = (uint32_t)(ks * 64 + t * 8);   // bytes into fp32 row
            const char* rowg = xb + (uint32_t)(wm * 16 + g) * XSTR + kb;
            const char* rowh = rowg + 8 * XSTR;
            const float2 x00 = *reinterpret_cast<const float2*>(rowg);
            const float2 x10 = *reinterpret_cast<const float2*>(rowh);
            const float2 x01 = *reinterpret_cast<const float2*>(rowg + 32);
            const float2 x11 = *reinterpret_cast<const float2*>(rowh + 32);
            uint32_t ah[4];
            ah[0] = hpack2(x00); ah[1] = hpack2(x10);
            ah[2] = hpack2(x01); ah[3] = hpack2(x11);

            uint32_t fh[2][4];
#pragma unroll
            for (int p = 0; p < 2; p++)
                ldm_x4(fh[p], b_addr(fb, wn * 32 + p * 16, lane, koff));

            if (isA) {
#pragma unroll
                for (int nt = 0; nt < 4; nt++)
                    mma_f16(acc[nt], ah, &fh[nt >> 1][(nt & 1) * 2]);
            } else {
                uint32_t al[4];
                al[0] = lpack2(x00, ah[0]); al[1] = lpack2(x10, ah[1]);
                al[2] = lpack2(x01, ah[2]); al[3] = lpack2(x11, ah[3]);
                uint32_t fl[2][4];
#pragma unroll
                for (int p = 0; p < 2; p++)
                    ldm_x4(fl[p], b_addr(fb + ARR, wn * 32 + p * 16, lane, koff));
#pragma unroll
                for (int nt = 0; nt < 4; nt++) {
                    const uint32_t* bh = &fh[nt >> 1][(nt & 1) * 2];
                    const uint32_t* bl = &fl[nt >> 1][(nt & 1) * 2];
                    mma_f16(acc[nt], ah, bh);
                    mma_f16(acc[nt], ah, bl);
                    mma_f16(acc[nt], al, bh);
                }
            }
        }
    }

    // Epilogue: a-rows -> Ph = fp16(relu(v)); b-rows -> Mb = fp16(v<=0)
#pragma unroll
    for (int nt = 0; nt < 4; nt++)
#pragma unroll
        for (int h = 0; h < 2; h++) {
            const int grow = m0 + wm * 16 + g + h * 8;
            const int col  = n0 + wn * 32 + nt * 8 + t * 2;
            const float v0 = acc[nt][h * 2 + 0];
            const float v1 = acc[nt][h * 2 + 1];
            if (isA) {
                const size_t idx = (size_t)grow * KK + col;
                *reinterpret_cast<__half2*>(g_Ph + idx) =
                    __half2(__float2half(fmaxf(v0, 0.0f)), __float2half(fmaxf(v1, 0.0f)));
            } else {
                const size_t idx = (size_t)(grow - NA) * KK + col;
                *reinterpret_cast<__half2*>(g_Mb + idx) =
                    __half2(__float2half(v0 <= 0.0f ? 1.0f : 0.0f),
                            __float2half(v1 <= 0.0f ? 1.0f : 0.0f));
            }
        }
}

// ---------------------------------------------------------------------------
// Stage 2: out[1024x1024] = Ph · Mb^T (fp16, fp32 accum)
// Tile 64(M) x 128(N), 256 threads (8 warps 2x4, warp tile 32x32),
// k-chunk 64, 3 buffers, 1 sync/chunk. grid (8, 16).
// ---------------------------------------------------------------------------
constexpr uint32_t S2_BUF = 3 * ARR;    // Ph 64 rows + Mb 128 rows
constexpr int S2_SMEM = 3 * S2_BUF;     // 82944

__global__ __launch_bounds__(256) void stage2_mma(float* __restrict__ out)
{
    extern __shared__ char dsm[];
    const uint32_t sb = smem_u32(dsm);

    const int tid = threadIdx.x;
    const int lane = tid & 31;
    const int wid = tid >> 5;
    const int wm = wid & 1;          // 2 warp rows x 32
    const int wn = wid >> 1;         // 4 warp cols x 32

    const int i0 = blockIdx.y * 64;
    const int j0 = blockIdx.x * 128;

    const __half* pPh = g_Ph + (size_t)i0 * KK;
    const __half* pMb = g_Mb + (size_t)j0 * KK;

    const int lr = tid >> 3, ls = tid & 7;
    auto load_chunk = [&](int ch, uint32_t buf) {
        const int k0 = ch * 64;
#pragma unroll
        for (int pass = 0; pass < 2; pass++) {
            const int r = lr + pass * 32;
            cp16(buf + (uint32_t)r * TSTR + (uint32_t)(ls << 4),
                 pPh + (size_t)r * KK + k0 + ls * 8);
        }
#pragma unroll
        for (int pass = 0; pass < 4; pass++) {
            const int r = lr + pass * 32;
            cp16(buf + ARR + (uint32_t)r * TSTR + (uint32_t)(ls << 4),
                 pMb + (size_t)r * KK + k0 + ls * 8);
        }
        cp_commit();
    };

    constexpr int NCH = KK / 64;   // 4
    load_chunk(0, sb);
    load_chunk(1, sb + S2_BUF);

    float acc[2][4][4] = {};

    for (int ch = 0; ch < NCH; ch++) {
        if (ch + 1 < NCH) cp_wait1(); else cp_wait0();
        __syncthreads();
        if (ch + 2 < NCH) load_chunk(ch + 2, sb + (uint32_t)((ch + 2) % 3) * S2_BUF);

        const uint32_t bb = sb + (uint32_t)(ch % 3) * S2_BUF;
#pragma unroll
        for (int ks = 0; ks < 4; ks++) {
            const int koff = ks * 32;
            uint32_t ph[2][4], mb[2][4];
#pragma unroll
            for (int mt = 0; mt < 2; mt++)
                ldm_x4(ph[mt], a_addr(bb, wm * 32 + mt * 16, lane, koff));
#pragma unroll
            for (int p = 0; p < 2; p++)
                ldm_x4(mb[p], b_addr(bb + ARR, wn * 32 + p * 16, lane, koff));
#pragma unroll
            for (int mt = 0; mt < 2; mt++)
#pragma unroll
                for (int nt = 0; nt < 4; nt++)
                    mma_f16(acc[mt][nt], ph[mt], &mb[nt >> 1][(nt & 1) * 2]);
        }
    }

#pragma unroll
    for (int mt = 0; mt < 2; mt++)
#pragma unroll
        for (int nt = 0; nt < 4; nt++)
#pragma unroll
            for (int h = 0; h < 2; h++) {
                const int row = i0 + wm * 32 + mt * 16 + (lane >> 2) + h * 8;
                const int col = j0 + wn * 32 + nt * 8 + (lane & 3) * 2;
                *reinterpret_cast<float2*>(out + (size_t)row * NB + col) =
                    make_float2(acc[mt][nt][h * 2 + 0], acc[mt][nt][h * 2 + 1]);
            }
}

// ---------------------------------------------------------------------------
extern "C" void kernel_launch(void* const* d_in, const int* in_sizes, int n_in,
                              void* d_out, int out_size)
{
    const float* a     = (const float*)d_in[0];
    const float* b     = (const float*)d_in[1];
    const float* feats = (const float*)d_in[2];
    float* out = (float*)d_out;
    (void)in_sizes; (void)n_in; (void)out_size;

    cudaFuncSetAttribute(stage1_mma, cudaFuncAttributeMaxDynamicSharedMemorySize, S1_SMEM);
    cudaFuncSetAttribute(stage2_mma, cudaFuncAttributeMaxDynamicSharedMemorySize, S2_SMEM);

    convertF_kernel<<<64, 256>>>(feats);
    stage1_mma<<<dim3(4, 32), 256, S1_SMEM>>>(a, b);
    stage2_mma<<<dim3(8, 16), 256, S2_SMEM>>>(out);
}

// round 10
// speedup vs baseline: 1.1218x; 1.1218x over previous
#include <cuda_runtime.h>
#include <cuda_fp16.h>
#include <cstdint>

constexpr int NA = 1024, NB = 1024, DD = 512, KK = 256;
constexpr int XROWS = NA + NB;
constexpr unsigned int GRID = 128;

// Device scratch
__device__ __half g_Xh[XROWS * DD];
__device__ __half g_Xl[NB * DD];
__device__ __half g_Fh[KK * DD];
__device__ __half g_Fl[KK * DD];
__device__ __half g_Ph[NA * KK];
__device__ __half g_Mb[NB * KK];
__device__ unsigned int g_bar_cnt;   // zero-init; monotonic across replays

// ---------------------------------------------------------------------------
// PTX helpers
// ---------------------------------------------------------------------------
__device__ __forceinline__ uint32_t smem_u32(const void* p) {
    uint32_t r;
    asm("{ .reg .u64 t; cvta.to.shared.u64 t, %1; cvt.u32.u64 %0, t; }" : "=r"(r) : "l"(p));
    return r;
}
__device__ __forceinline__ void cp16(uint32_t dst, const void* src) {
    asm volatile("cp.async.cg.shared.global [%0], [%1], 16;" :: "r"(dst), "l"(src) : "memory");
}
__device__ __forceinline__ void cp_commit() { asm volatile("cp.async.commit_group;" ::: "memory"); }
__device__ __forceinline__ void cp_wait1()  { asm volatile("cp.async.wait_group 1;" ::: "memory"); }
__device__ __forceinline__ void cp_wait0()  { asm volatile("cp.async.wait_group 0;" ::: "memory"); }

__device__ __forceinline__ void ldm_x4(uint32_t* r, uint32_t addr) {
    asm volatile("ldmatrix.sync.aligned.m8n8.x4.shared.b16 {%0,%1,%2,%3}, [%4];"
                 : "=r"(r[0]), "=r"(r[1]), "=r"(r[2]), "=r"(r[3]) : "r"(addr));
}
__device__ __forceinline__ void mma_f16(float* d, const uint32_t* a, const uint32_t* b) {
    asm volatile(
        "mma.sync.aligned.m16n8k16.row.col.f32.f16.f16.f32 "
        "{%0,%1,%2,%3}, {%4,%5,%6,%7}, {%8,%9}, {%0,%1,%2,%3};"
        : "+f"(d[0]), "+f"(d[1]), "+f"(d[2]), "+f"(d[3])
        : "r"(a[0]), "r"(a[1]), "r"(a[2]), "r"(a[3]), "r"(b[0]), "r"(b[1]));
}

constexpr uint32_t TSTR = 144;
constexpr uint32_t ARR  = 64 * TSTR;   // 9216

__device__ __forceinline__ uint32_t a_addr(uint32_t base, int row0, int lane, int koff) {
    return base + (uint32_t)(row0 + (lane & 15)) * TSTR + (uint32_t)koff + ((lane >> 4) << 4);
}
__device__ __forceinline__ uint32_t b_addr(uint32_t base, int row0, int lane, int koff) {
    return base + (uint32_t)(row0 + (lane & 7) + ((lane >> 4) << 3)) * TSTR
                + (uint32_t)koff + (((lane >> 3) & 1) << 4);
}

// Grid-wide barrier: all GRID CTAs co-resident (1 CTA/SM, grid <= #SM).
// Monotonic counter is replay-safe: arrivals of one barrier instance form a
// contiguous block, so target = end of my block.
__device__ __forceinline__ void grid_barrier() {
    __syncthreads();
    if (threadIdx.x == 0) {
        __threadfence();
        const unsigned int arrival = atomicAdd(&g_bar_cnt, 1u);
        const unsigned int target = (arrival / GRID + 1u) * GRID;
        unsigned int v;
        do {
            asm volatile("ld.acquire.gpu.u32 %0, [%1];" : "=r"(v) : "l"(&g_bar_cnt));
        } while (v < target);
    }
    __syncthreads();
}

// fp32 -> fp16 split packers
__device__ __forceinline__ uint32_t hpack(float x, float y) {
    __half2 t = __float22half2_rn(make_float2(x, y));
    return *reinterpret_cast<uint32_t*>(&t);
}
__device__ __forceinline__ uint4 hi4(const float4& v0, const float4& v1) {
    return make_uint4(hpack(v0.x, v0.y), hpack(v0.z, v0.w),
                      hpack(v1.x, v1.y), hpack(v1.z, v1.w));
}
__device__ __forceinline__ uint4 lo4(const float4& v0, const float4& v1) {
    float l[8];
    const float xs[8] = {v0.x, v0.y, v0.z, v0.w, v1.x, v1.y, v1.z, v1.w};
#pragma unroll
    for (int i = 0; i < 8; i++)
        l[i] = xs[i] - __half2float(__float2half(xs[i]));
    return make_uint4(hpack(l[0], l[1]), hpack(l[2], l[3]),
                      hpack(l[4], l[5]), hpack(l[6], l[7]));
}

// smem layout (shared across phases)
constexpr uint32_t S1_BUF = 4 * ARR;              // Xh, Xl, Fh, Fl
constexpr int S1_SMEM = 3 * S1_BUF;               // 110592
constexpr uint32_t S2_BUF = 3 * ARR;              // Ph(64) + Mb(128)
constexpr int SMEM_DYN = S1_SMEM;                 // >= 3*S2_BUF = 82944

// ---------------------------------------------------------------------------
__global__ __launch_bounds__(256, 1) void fused_kernel(
    const float* __restrict__ a, const float* __restrict__ b,
    const float* __restrict__ feats, float* __restrict__ out)
{
    extern __shared__ char dsm[];
    const uint32_t sb = smem_u32(dsm);

    const int tid = threadIdx.x;
    const int bid = blockIdx.x;
    const int lane = tid & 31;
    const int wid = tid >> 5;
    const int gt = bid * 256 + tid;      // 0..32767

    // =======================================================================
    // Phase 0: convert. a: hi only; b: hi+lo; feats: hi+lo.
    // =======================================================================
    {
        // a: 65536 float4 -> 2 per thread (hi only)
#pragma unroll
        for (int k = 0; k < 2; k++) {
            const int base = (gt + k * 32768) * 8;
            const float4 v0 = *reinterpret_cast<const float4*>(a + base);
            const float4 v1 = *reinterpret_cast<const float4*>(a + base + 4);
            *reinterpret_cast<uint4*>(g_Xh + base) = hi4(v0, v1);
        }
        // b: 2 per thread (hi + lo)
#pragma unroll
        for (int k = 0; k < 2; k++) {
            const int base = (gt + k * 32768) * 8;
            const float4 v0 = *reinterpret_cast<const float4*>(b + base);
            const float4 v1 = *reinterpret_cast<const float4*>(b + base + 4);
            *reinterpret_cast<uint4*>(g_Xh + NA * DD + base) = hi4(v0, v1);
            *reinterpret_cast<uint4*>(g_Xl + base)           = lo4(v0, v1);
        }
        // feats: 16384 x 8 floats -> first half of threads
        if (gt < 16384) {
            const int base = gt * 8;
            const float4 v0 = *reinterpret_cast<const float4*>(feats + base);
            const float4 v1 = *reinterpret_cast<const float4*>(feats + base + 4);
            *reinterpret_cast<uint4*>(g_Fh + base) = hi4(v0, v1);
            *reinterpret_cast<uint4*>(g_Fl + base) = lo4(v0, v1);
        }
    }

    grid_barrier();

    // =======================================================================
    // Phase 1: stage1 — C[2048x256] = X · F^T
    //   a rows: Xh·Fh ; b rows: XhFh + XhFl + XlFh
    // Tile 64x64, warp tile 16x32, k-chunk 64, 3 buffers, 1 sync/chunk.
    // =======================================================================
    {
        const int wm = wid & 3;          // 4 warp rows x 16
        const int wn = wid >> 2;         // 2 warp cols x 32
        const int m0 = (bid >> 2) * 64;  // 32 m-tiles
        const int n0 = (bid & 3) * 64;   // 4 n-tiles
        const bool isA = (m0 < NA);

        const __half* pXh = g_Xh + (size_t)m0 * DD;
        const __half* pXl = g_Xl + (size_t)(isA ? 0 : m0 - NA) * DD;
        const __half* pFh = g_Fh + (size_t)n0 * DD;
        const __half* pFl = g_Fl + (size_t)n0 * DD;

        const int lr = tid >> 3, ls = tid & 7;
        auto load_chunk = [&](int ch, uint32_t buf) {
            const int d0 = ch * 64;
#pragma unroll
            for (int pass = 0; pass < 2; pass++) {
                const int r = lr + pass * 32;
                const size_t off = (size_t)r * DD + d0 + ls * 8;
                const uint32_t sm = buf + (uint32_t)r * TSTR + (uint32_t)(ls << 4);
                cp16(sm + 0 * ARR, pXh + off);
                cp16(sm + 2 * ARR, pFh + off);
                if (!isA) {
                    cp16(sm + 1 * ARR, pXl + off);
                    cp16(sm + 3 * ARR, pFl + off);
                }
            }
            cp_commit();
        };

        constexpr int NCH = DD / 64;   // 8
        load_chunk(0, sb);
        load_chunk(1, sb + S1_BUF);

        float acc[4][4] = {};

        for (int ch = 0; ch < NCH; ch++) {
            if (ch + 1 < NCH) cp_wait1(); else cp_wait0();
            __syncthreads();
            if (ch + 2 < NCH) load_chunk(ch + 2, sb + (uint32_t)((ch + 2) % 3) * S1_BUF);

            const uint32_t bb = sb + (uint32_t)(ch % 3) * S1_BUF;
#pragma unroll
            for (int ks = 0; ks < 4; ks++) {
                const int koff = ks * 32;
                uint32_t ah[4], fh[2][4];
                ldm_x4(ah, a_addr(bb + 0 * ARR, wm * 16, lane, koff));
#pragma unroll
                for (int p = 0; p < 2; p++)
                    ldm_x4(fh[p], b_addr(bb + 2 * ARR, wn * 32 + p * 16, lane, koff));
                if (isA) {
#pragma unroll
                    for (int nt = 0; nt < 4; nt++)
                        mma_f16(acc[nt], ah, &fh[nt >> 1][(nt & 1) * 2]);
                } else {
                    uint32_t al[4], fl[2][4];
                    ldm_x4(al, a_addr(bb + 1 * ARR, wm * 16, lane, koff));
#pragma unroll
                    for (int p = 0; p < 2; p++)
                        ldm_x4(fl[p], b_addr(bb + 3 * ARR, wn * 32 + p * 16, lane, koff));
#pragma unroll
                    for (int nt = 0; nt < 4; nt++) {
                        const uint32_t* bh = &fh[nt >> 1][(nt & 1) * 2];
                        const uint32_t* bl = &fl[nt >> 1][(nt & 1) * 2];
                        mma_f16(acc[nt], ah, bh);
                        mma_f16(acc[nt], ah, bl);
                        mma_f16(acc[nt], al, bh);
                    }
                }
            }
        }

        // Epilogue
#pragma unroll
        for (int nt = 0; nt < 4; nt++)
#pragma unroll
            for (int h = 0; h < 2; h++) {
                const int grow = m0 + wm * 16 + (lane >> 2) + h * 8;
                const int col  = n0 + wn * 32 + nt * 8 + (lane & 3) * 2;
                const float v0 = acc[nt][h * 2 + 0];
                const float v1 = acc[nt][h * 2 + 1];
                if (isA) {
                    const size_t idx = (size_t)grow * KK + col;
                    *reinterpret_cast<__half2*>(g_Ph + idx) =
                        __half2(__float2half(fmaxf(v0, 0.0f)), __float2half(fmaxf(v1, 0.0f)));
                } else {
                    const size_t idx = (size_t)(grow - NA) * KK + col;
                    *reinterpret_cast<__half2*>(g_Mb + idx) =
                        __half2(__float2half(v0 <= 0.0f ? 1.0f : 0.0f),
                                __float2half(v1 <= 0.0f ? 1.0f : 0.0f));
                }
            }
    }

    grid_barrier();

    // =======================================================================
    // Phase 2: stage2 — out[1024x1024] = Ph · Mb^T
    // Tile 64(M) x 128(N), warp tile 32x32, k-chunk 64, 3 buffers.
    // =======================================================================
    {
        const int wm = wid & 1;          // 2 warp rows x 32
        const int wn = wid >> 1;         // 4 warp cols x 32
        const int i0 = (bid >> 3) * 64;  // 16 i-tiles
        const int j0 = (bid & 7) * 128;  // 8 j-tiles

        const __half* pPh = g_Ph + (size_t)i0 * KK;
        const __half* pMb = g_Mb + (size_t)j0 * KK;

        const int lr = tid >> 3, ls = tid & 7;
        auto load_chunk = [&](int ch, uint32_t buf) {
            const int k0 = ch * 64;
#pragma unroll
            for (int pass = 0; pass < 2; pass++) {
                const int r = lr + pass * 32;
                cp16(buf + (uint32_t)r * TSTR + (uint32_t)(ls << 4),
                     pPh + (size_t)r * KK + k0 + ls * 8);
            }
#pragma unroll
            for (int pass = 0; pass < 4; pass++) {
                const int r = lr + pass * 32;
                cp16(buf + ARR + (uint32_t)r * TSTR + (uint32_t)(ls << 4),
                     pMb + (size_t)r * KK + k0 + ls * 8);
            }
            cp_commit();
        };

        constexpr int NCH = KK / 64;   // 4
        load_chunk(0, sb);
        load_chunk(1, sb + S2_BUF);

        float acc[2][4][4] = {};

        for (int ch = 0; ch < NCH; ch++) {
            if (ch + 1 < NCH) cp_wait1(); else cp_wait0();
            __syncthreads();
            if (ch + 2 < NCH) load_chunk(ch + 2, sb + (uint32_t)((ch + 2) % 3) * S2_BUF);

            const uint32_t bb = sb + (uint32_t)(ch % 3) * S2_BUF;
#pragma unroll
            for (int ks = 0; ks < 4; ks++) {
                const int koff = ks * 32;
                uint32_t ph[2][4], mb[2][4];
#pragma unroll
                for (int mt = 0; mt < 2; mt++)
                    ldm_x4(ph[mt], a_addr(bb, wm * 32 + mt * 16, lane, koff));
#pragma unroll
                for (int p = 0; p < 2; p++)
                    ldm_x4(mb[p], b_addr(bb + ARR, wn * 32 + p * 16, lane, koff));
#pragma unroll
                for (int mt = 0; mt < 2; mt++)
#pragma unroll
                    for (int nt = 0; nt < 4; nt++)
                        mma_f16(acc[mt][nt], ph[mt], &mb[nt >> 1][(nt & 1) * 2]);
            }
        }

#pragma unroll
        for (int mt = 0; mt < 2; mt++)
#pragma unroll
            for (int nt = 0; nt < 4; nt++)
#pragma unroll
                for (int h = 0; h < 2; h++) {
                    const int row = i0 + wm * 32 + mt * 16 + (lane >> 2) + h * 8;
                    const int col = j0 + wn * 32 + nt * 8 + (lane & 3) * 2;
                    *reinterpret_cast<float2*>(out + (size_t)row * NB + col) =
                        make_float2(acc[mt][nt][h * 2 + 0], acc[mt][nt][h * 2 + 1]);
                }
    }
}

// ---------------------------------------------------------------------------
extern "C" void kernel_launch(void* const* d_in, const int* in_sizes, int n_in,
                              void* d_out, int out_size)
{
    const float* a     = (const float*)d_in[0];
    const float* b     = (const float*)d_in[1];
    const float* feats = (const float*)d_in[2];
    float* out = (float*)d_out;
    (void)in_sizes; (void)n_in; (void)out_size;

    cudaFuncSetAttribute(fused_kernel, cudaFuncAttributeMaxDynamicSharedMemorySize, SMEM_DYN);
    fused_kernel<<<GRID, 256, SMEM_DYN>>>(a, b, feats, out);
}